// round 7
// baseline (speedup 1.0000x reference)
#include <cuda_runtime.h>

typedef unsigned long long ull;

#define HID   128
#define TT    512
#define NB    2048
#define RPC   8
#define NCTA  (NB / RPC)   // 256
#define NTHR  256

// Blocked weights: [kq][gate*128+j][k%4] -> 16B load at (kq,g,j) = W[g,j][4 consecutive k]
// 0: Wh0, 1: Wi1, 2: Wh1
__device__ __align__(16) float g_wt[3][128 * 384];

__global__ void transpose_k(const float* __restrict__ Wh0,
                            const float* __restrict__ Wi1,
                            const float* __restrict__ Wh1) {
    int idx = blockIdx.x * blockDim.x + threadIdx.x;
    if (idx >= 128 * 384) return;
    int kq  = idx / 1536;
    int rem = idx - kq * 1536;
    int gj  = rem >> 2;
    int k   = kq * 4 + (rem & 3);
    g_wt[0][idx] = Wh0[gj * HID + k];
    g_wt[1][idx] = Wi1[gj * HID + k];
    g_wt[2][idx] = Wh1[gj * HID + k];
}

// ---- packed f32x2 helpers ----
__device__ __forceinline__ void ffma2(ull& d, ull a, ull b) {
    asm("fma.rn.f32x2 %0, %1, %2, %0;" : "+l"(d) : "l"(a), "l"(b));
}
__device__ __forceinline__ float hadd2(ull v) {
    float lo, hi; asm("mov.b64 {%0, %1}, %2;" : "=f"(lo), "=f"(hi) : "l"(v)); return lo + hi;
}
__device__ __forceinline__ float tanhap(float x) {
    float y; asm("tanh.approx.f32 %0, %1;" : "=f"(y) : "f"(x)); return y;
}
__device__ __forceinline__ float sigap(float x) {
    return fmaf(tanhap(0.5f * x), 0.5f, 0.5f);
}

__global__ void __launch_bounds__(NTHR, 2)
gru_kernel(const float* __restrict__ x,
           const float* __restrict__ noise_z,
           const float* __restrict__ context,
           const float* __restrict__ Wi0,
           const float* __restrict__ bi0,
           const float* __restrict__ bh0,
           const float* __restrict__ bi1,
           const float* __restrict__ bh1,
           const float* __restrict__ Wa,
           const float* __restrict__ ba,
           float* __restrict__ out) {
    __shared__ __align__(16) float h0s[RPC][128];     // [r][k], owned+updated by group A
    __shared__ __align__(16) float h1s[RPC][128];     // [r][k], owned+updated by group B
    __shared__ __align__(16) float red[2][RPC][128];  // Ui r,z partials (A -> B)
    __shared__ __align__(16) float was[256];          // Wa staged
    __shared__ __align__(16) float decs[2][RPC];      // feedback [s][r] (B -> A)

    const int tid = threadIdx.x;
    const int grp = tid >> 7;          // 0: layer-0 + Ui r,z ; 1: Wh1 + Ui n + epi1 + head
    const int j   = tid & 127;
    const int brow0 = blockIdx.x * RPC;

    // ---- init ----
    for (int i = tid; i < RPC * 128; i += NTHR) {
        (&h0s[0][0])[i] = 0.f;
        (&h1s[0][0])[i] = 0.f;
    }
    was[tid] = Wa[tid];
    if (tid < 2 * RPC) {
        int r = tid >> 1, s = tid & 1;
        decs[s][r] = noise_z[(brow0 + r) * 2 + s];
    }

    // per-thread constants
    const float bh0r = bh0[j], bh0z = bh0[128 + j], bh0n = bh0[256 + j];
    const float brzr = bi1[j] + bh1[j];
    const float brzz = bi1[128 + j] + bh1[128 + j];
    const float binn = bi1[256 + j];
    const float bhnn = bh1[256 + j];
    float wd0[3], wd1[3];
#pragma unroll
    for (int g = 0; g < 3; ++g) {
        wd0[g] = Wi0[(g * 128 + j) * 12 + 0];
        wd1[g] = Wi0[(g * 128 + j) * 12 + 1];
    }

    // ctx gates (bi0 + context part) for all 8 rows (used by group A only)
    float cg[3][8];
#pragma unroll
    for (int g = 0; g < 3; ++g) {
        int gj = g * 128 + j;
        float wrow[10];
#pragma unroll
        for (int e = 0; e < 10; ++e) wrow[e] = Wi0[gj * 12 + 2 + e];
        float b = bi0[gj];
        for (int r = 0; r < RPC; ++r) {
            float acc = b;
#pragma unroll
            for (int e = 0; e < 10; ++e) acc += context[(brow0 + r) * 10 + e] * wrow[e];
            cg[g][r] = acc;
        }
    }

    // head role (group B): j -> (row hr, state hs, k-slice hl)
    const int hr = j >> 4;
    const int hs = (j >> 3) & 1;
    const int hl = j & 7;
    const float bas = ba[hs];

    const ulonglong2* wb0 = reinterpret_cast<const ulonglong2*>(g_wt[0]) + j;  // Wh0
    const ulonglong2* wbu = reinterpret_cast<const ulonglong2*>(g_wt[1]) + j;  // Wi1
    const ulonglong2* wbv = reinterpret_cast<const ulonglong2*>(g_wt[2]) + j;  // Wh1

    // group-dependent phase-1 operands (uniform code below)
    const ulonglong2* p1 = grp ? wbv : wb0;
    const float (*hsrc)[128] = grp ? h1s : h0s;

    __syncthreads();

    for (int t = -1; t < TT; ++t) {
        // ===== phase 1 (symmetric): A: Wh0 @ h0_old ; B: Wh1 @ h1_old =====
        ull C0[8], C1[8], C2[8];
#pragma unroll
        for (int rr = 0; rr < 8; ++rr) { C0[rr] = 0ull; C1[rr] = 0ull; C2[rr] = 0ull; }
#pragma unroll 2
        for (int kq = 0; kq < 32; ++kq) {
            ulonglong2 w0 = p1[kq * 384];
            ulonglong2 w1 = p1[kq * 384 + 128];
            ulonglong2 w2 = p1[kq * 384 + 256];
#pragma unroll
            for (int rr = 0; rr < 8; ++rr) {
                ulonglong2 h = *reinterpret_cast<const ulonglong2*>(&hsrc[rr][kq * 4]);
                ffma2(C0[rr], w0.x, h.x); ffma2(C0[rr], w0.y, h.y);
                ffma2(C1[rr], w1.x, h.x); ffma2(C1[rr], w1.y, h.y);
                ffma2(C2[rr], w2.x, h.x); ffma2(C2[rr], w2.y, h.y);
            }
        }
        __syncthreads();   // S0: prev-step decs written (B) / h-arrays fully read

        // ===== layer-0 epilogue: group A alone, all 8 rows, no exchange =====
        if (grp == 0) {
#pragma unroll
            for (int r = 0; r < RPC; ++r) {
                float d0 = decs[0][r], d1 = decs[1][r];
                float rg = sigap(cg[0][r] + d0 * wd0[0] + d1 * wd1[0] + hadd2(C0[r]) + bh0r);
                float zg = sigap(cg[1][r] + d0 * wd0[1] + d1 * wd1[1] + hadd2(C1[r]) + bh0z);
                float ng = tanhap(cg[2][r] + d0 * wd0[2] + d1 * wd1[2] +
                                  rg * (hadd2(C2[r]) + bh0n));
                float ho = h0s[r][j];
                h0s[r][j] = ng + zg * (ho - ng);
            }
        }
        __syncthreads();   // S1: h0_new visible

        // ===== phase 2: Ui @ h0_new (A: r,z -> red ; B: n -> regs) =====
        if (grp == 0) {
            ull D0[8], D1[8];
#pragma unroll
            for (int rr = 0; rr < 8; ++rr) { D0[rr] = 0ull; D1[rr] = 0ull; }
#pragma unroll 2
            for (int kq = 0; kq < 32; ++kq) {
                ulonglong2 u0 = wbu[kq * 384];
                ulonglong2 u1 = wbu[kq * 384 + 128];
#pragma unroll
                for (int rr = 0; rr < 8; ++rr) {
                    ulonglong2 h = *reinterpret_cast<const ulonglong2*>(&h0s[rr][kq * 4]);
                    ffma2(D0[rr], u0.x, h.x); ffma2(D0[rr], u0.y, h.y);
                    ffma2(D1[rr], u1.x, h.x); ffma2(D1[rr], u1.y, h.y);
                }
            }
#pragma unroll
            for (int r = 0; r < RPC; ++r) {
                red[0][r][j] = hadd2(D0[r]);
                red[1][r][j] = hadd2(D1[r]);
            }
            __syncthreads();   // S2: red visible; A proceeds straight to next phase 1
        } else {
            ull D0[8];
#pragma unroll
            for (int rr = 0; rr < 8; ++rr) D0[rr] = 0ull;
#pragma unroll 2
            for (int kq = 0; kq < 32; ++kq) {
                ulonglong2 u2 = wbu[kq * 384 + 256];
#pragma unroll
                for (int rr = 0; rr < 8; ++rr) {
                    ulonglong2 h = *reinterpret_cast<const ulonglong2*>(&h0s[rr][kq * 4]);
                    ffma2(D0[rr], u2.x, h.x); ffma2(D0[rr], u2.y, h.y);
                }
            }
            __syncthreads();   // S2

            // ===== layer-1 epilogue: group B alone =====
#pragma unroll
            for (int r = 0; r < RPC; ++r) {
                float rg = sigap(red[0][r][j] + hadd2(C0[r]) + brzr);
                float zg = sigap(red[1][r][j] + hadd2(C1[r]) + brzz);
                float ng = tanhap(hadd2(D0[r]) + binn + rg * (hadd2(C2[r]) + bhnn));
                float ho = h1s[r][j];
                h1s[r][j] = ng + zg * (ho - ng);
            }

            // ===== output head + autoregressive feedback (group B) =====
            if (t >= 0) {
                asm volatile("bar.sync 1, 128;" ::: "memory");   // B-only: h1_new visible
                ull acc = 0ull;
                const float* hrow = &h1s[hr][hl * 16];
                const float* wrow = &was[hs * 128 + hl * 16];
#pragma unroll
                for (int qq = 0; qq < 4; ++qq) {
                    ulonglong2 hv = *reinterpret_cast<const ulonglong2*>(&hrow[qq * 4]);
                    ulonglong2 wv = *reinterpret_cast<const ulonglong2*>(&wrow[qq * 4]);
                    ffma2(acc, wv.x, hv.x);
                    ffma2(acc, wv.y, hv.y);
                }
                float v = hadd2(acc);
                v += __shfl_xor_sync(0xffffffffu, v, 1, 8);
                v += __shfl_xor_sync(0xffffffffu, v, 2, 8);
                v += __shfl_xor_sync(0xffffffffu, v, 4, 8);
                if (hl == 0) {
                    float o = v + bas;
                    decs[hs][hr] = o;
                    out[(size_t)(brow0 + hr) * (TT * 2) + t * 2 + hs] = o;
                }
            } else {
                if (j < 2 * RPC) {
                    int r = j >> 1, s = j & 1;
                    decs[s][r] = x[(size_t)(brow0 + r) * (TT * 2) + s];
                }
            }
            // decs/h1s ordered for A and for B's next phase-1 by next iteration's S0
        }
    }
}

extern "C" void kernel_launch(void* const* d_in, const int* in_sizes, int n_in,
                              void* d_out, int out_size) {
    const float* x       = (const float*)d_in[0];
    const float* noise_z = (const float*)d_in[1];
    const float* context = (const float*)d_in[2];
    const float* Wi0     = (const float*)d_in[3];
    const float* Wh0     = (const float*)d_in[4];
    const float* bi0     = (const float*)d_in[5];
    const float* bh0     = (const float*)d_in[6];
    const float* Wi1     = (const float*)d_in[7];
    const float* Wh1     = (const float*)d_in[8];
    const float* bi1     = (const float*)d_in[9];
    const float* bh1     = (const float*)d_in[10];
    const float* Wa      = (const float*)d_in[11];
    const float* ba      = (const float*)d_in[12];
    float* out = (float*)d_out;

    transpose_k<<<192, 256>>>(Wh0, Wi1, Wh1);
    gru_kernel<<<NCTA, NTHR>>>(x, noise_z, context, Wi0, bi0, bh0,
                               bi1, bh1, Wa, ba, out);
}

// round 8
// speedup vs baseline: 1.1037x; 1.1037x over previous
#include <cuda_runtime.h>

typedef unsigned long long ull;

#define HID   128
#define TT    512
#define NB    2048
#define RPC   8
#define NCTA  (NB / RPC)   // 256
#define NTHR  256

// Blocked weights: [kq][gate*128+j][k%4] -> 16B load at (kq,g,j) = W[g,j][4 consecutive k]
// 0: Wh0, 1: Wi1, 2: Wh1
__device__ __align__(16) float g_wt[3][128 * 384];

__global__ void transpose_k(const float* __restrict__ Wh0,
                            const float* __restrict__ Wi1,
                            const float* __restrict__ Wh1) {
    int idx = blockIdx.x * blockDim.x + threadIdx.x;
    if (idx >= 128 * 384) return;
    int kq  = idx / 1536;
    int rem = idx - kq * 1536;
    int gj  = rem >> 2;
    int k   = kq * 4 + (rem & 3);
    g_wt[0][idx] = Wh0[gj * HID + k];
    g_wt[1][idx] = Wi1[gj * HID + k];
    g_wt[2][idx] = Wh1[gj * HID + k];
}

// ---- packed f32x2 helpers ----
__device__ __forceinline__ void ffma2(ull& d, ull a, ull b) {
    asm("fma.rn.f32x2 %0, %1, %2, %0;" : "+l"(d) : "l"(a), "l"(b));
}
__device__ __forceinline__ float hadd2(ull v) {
    float lo, hi; asm("mov.b64 {%0, %1}, %2;" : "=f"(lo), "=f"(hi) : "l"(v)); return lo + hi;
}
__device__ __forceinline__ float tanhap(float x) {
    float y; asm("tanh.approx.f32 %0, %1;" : "=f"(y) : "f"(x)); return y;
}
__device__ __forceinline__ float sigap(float x) {
    return fmaf(tanhap(0.5f * x), 0.5f, 0.5f);
}

__global__ void __launch_bounds__(NTHR, 2)
gru_kernel(const float* __restrict__ x,
           const float* __restrict__ noise_z,
           const float* __restrict__ context,
           const float* __restrict__ Wi0,
           const float* __restrict__ bi0,
           const float* __restrict__ bh0,
           const float* __restrict__ bi1,
           const float* __restrict__ bh1,
           const float* __restrict__ Wa,
           const float* __restrict__ ba,
           float* __restrict__ out) {
    __shared__ __align__(16) float h0s[2][RPC][128];   // [buf][r][k]
    __shared__ __align__(16) float h1s[2][RPC][128];
    __shared__ __align__(16) float ctxgi[3][RPC][128]; // [g][r][j]
    __shared__ __align__(16) float was[256];           // Wa staged
    __shared__ __align__(16) float decs[2][RPC];       // feedback [s][r]

    const int tid = threadIdx.x;
    const int hf  = tid >> 7;          // row-half
    const int j   = tid & 127;         // output neuron
    const int r0  = hf * 4;            // 4 rows per thread
    const int brow0 = blockIdx.x * RPC;

    // ---- init ----
    for (int i = tid; i < 2 * RPC * 128; i += NTHR) {
        (&h0s[0][0][0])[i] = 0.f;
        (&h1s[0][0][0])[i] = 0.f;
    }
    was[tid] = Wa[tid];
    if (tid < 2 * RPC) {
        int r = tid >> 1, s = tid & 1;
        decs[s][r] = noise_z[(brow0 + r) * 2 + s];
    }

    // per-thread constants
    const float bh0r = bh0[j], bh0z = bh0[128 + j], bh0n = bh0[256 + j];
    const float brzr = bi1[j] + bh1[j];
    const float brzz = bi1[128 + j] + bh1[128 + j];
    const float binn = bi1[256 + j];
    const float bhnn = bh1[256 + j];
    float wd0[3], wd1[3];
#pragma unroll
    for (int g = 0; g < 3; ++g) {
        wd0[g] = Wi0[(g * 128 + j) * 12 + 0];
        wd1[g] = Wi0[(g * 128 + j) * 12 + 1];
    }

    // ctx gates: bi0 + context-part (time invariant)
#pragma unroll
    for (int g = 0; g < 3; ++g) {
        int gj = g * 128 + j;
        float wrow[10];
#pragma unroll
        for (int e = 0; e < 10; ++e) wrow[e] = Wi0[gj * 12 + 2 + e];
        float b = bi0[gj];
        for (int q = 0; q < 4; ++q) {
            int r = r0 + q;
            float acc = b;
#pragma unroll
            for (int e = 0; e < 10; ++e) acc += context[(brow0 + r) * 10 + e] * wrow[e];
            ctxgi[g][r][j] = acc;
        }
    }

    // head role (threads 0..127): (row hr, state hs, k-slice hl)
    const int hr = (tid >> 4) & 7;
    const int hs = (tid >> 3) & 1;
    const int hl = tid & 7;
    const float bas = ba[hs];

    const ulonglong2* w0b = reinterpret_cast<const ulonglong2*>(g_wt[0]) + j;
    const ulonglong2* wib = reinterpret_cast<const ulonglong2*>(g_wt[1]) + j;
    const ulonglong2* whb = reinterpret_cast<const ulonglong2*>(g_wt[2]) + j;

    __syncthreads();

    // --- weight pipeline registers: L0 kq=0 preloaded before the time loop ---
    ulonglong2 cA = w0b[0], cB = w0b[128], cC = w0b[256];

    int p = 0;
    for (int t = -1; t < TT; ++t) {
        // ================= layer 0: gh0 = h0_old @ Wh0^T (pipelined) =========
        ull A0[4], A1[4], A2[4];
#pragma unroll
        for (int rr = 0; rr < 4; ++rr) { A0[rr] = 0ull; A1[rr] = 0ull; A2[rr] = 0ull; }
        {
            const float (*hb)[128] = h0s[p];
#pragma unroll 4
            for (int kq = 0; kq < 32; ++kq) {
                ulonglong2 nA, nB, nC;
                if (kq + 1 < 32) {
                    nA = w0b[(kq + 1) * 384];
                    nB = w0b[(kq + 1) * 384 + 128];
                    nC = w0b[(kq + 1) * 384 + 256];
                }
#pragma unroll
                for (int rr = 0; rr < 4; ++rr) {
                    ulonglong2 h = *reinterpret_cast<const ulonglong2*>(&hb[r0 + rr][kq * 4]);
                    ffma2(A0[rr], cA.x, h.x); ffma2(A0[rr], cA.y, h.y);
                    ffma2(A1[rr], cB.x, h.x); ffma2(A1[rr], cB.y, h.y);
                    ffma2(A2[rr], cC.x, h.x); ffma2(A2[rr], cC.y, h.y);
                }
                cA = nA; cB = nB; cC = nC;
            }
        }

        // cross-barrier prefetch: L1 phase kq=0 weights (h-independent)
        ulonglong2 cu0 = wib[0], cu1 = wib[128], cu2 = wib[256];
        ulonglong2 cv0 = whb[0], cv1 = whb[128], cv2 = whb[256];

        // layer-0 epilogue: 4 rows
#pragma unroll
        for (int rr = 0; rr < 4; ++rr) {
            int r = r0 + rr;
            float d0 = decs[0][r], d1 = decs[1][r];
            float rg = sigap(ctxgi[0][r][j] + d0 * wd0[0] + d1 * wd1[0] + hadd2(A0[rr]) + bh0r);
            float zg = sigap(ctxgi[1][r][j] + d0 * wd0[1] + d1 * wd1[1] + hadd2(A1[rr]) + bh0z);
            float ng = tanhap(ctxgi[2][r][j] + d0 * wd0[2] + d1 * wd1[2] +
                              rg * (hadd2(A2[rr]) + bh0n));
            float ho = h0s[p][r][j];
            h0s[p ^ 1][r][j] = ng + zg * (ho - ng);
        }
        __syncthreads();   // new h0 visible

        // ====== layer 1: gi1 (r/z fused with gh1); n split (pipelined) ======
        ull Z0[4], Z1[4], Ni[4], Nh[4];
#pragma unroll
        for (int rr = 0; rr < 4; ++rr) { Z0[rr] = 0ull; Z1[rr] = 0ull; Ni[rr] = 0ull; Nh[rr] = 0ull; }
        {
            const float (*ha)[128] = h0s[p ^ 1];
            const float (*hb)[128] = h1s[p];
#pragma unroll 2
            for (int kq = 0; kq < 32; ++kq) {
                ulonglong2 nu0, nu1, nu2, nv0, nv1, nv2;
                if (kq + 1 < 32) {
                    nu0 = wib[(kq + 1) * 384];
                    nu1 = wib[(kq + 1) * 384 + 128];
                    nu2 = wib[(kq + 1) * 384 + 256];
                    nv0 = whb[(kq + 1) * 384];
                    nv1 = whb[(kq + 1) * 384 + 128];
                    nv2 = whb[(kq + 1) * 384 + 256];
                }
#pragma unroll
                for (int rr = 0; rr < 4; ++rr) {
                    ulonglong2 a = *reinterpret_cast<const ulonglong2*>(&ha[r0 + rr][kq * 4]);
                    ulonglong2 b = *reinterpret_cast<const ulonglong2*>(&hb[r0 + rr][kq * 4]);
                    ffma2(Z0[rr], cu0.x, a.x); ffma2(Z0[rr], cu0.y, a.y);
                    ffma2(Z0[rr], cv0.x, b.x); ffma2(Z0[rr], cv0.y, b.y);
                    ffma2(Z1[rr], cu1.x, a.x); ffma2(Z1[rr], cu1.y, a.y);
                    ffma2(Z1[rr], cv1.x, b.x); ffma2(Z1[rr], cv1.y, b.y);
                    ffma2(Ni[rr], cu2.x, a.x); ffma2(Ni[rr], cu2.y, a.y);
                    ffma2(Nh[rr], cv2.x, b.x); ffma2(Nh[rr], cv2.y, b.y);
                }
                cu0 = nu0; cu1 = nu1; cu2 = nu2;
                cv0 = nv0; cv1 = nv1; cv2 = nv2;
            }
        }

        // cross-barrier prefetch: next step's L0 kq=0 weights
        cA = w0b[0]; cB = w0b[128]; cC = w0b[256];

        // layer-1 epilogue
#pragma unroll
        for (int rr = 0; rr < 4; ++rr) {
            int r = r0 + rr;
            float rg = sigap(hadd2(Z0[rr]) + brzr);
            float zg = sigap(hadd2(Z1[rr]) + brzz);
            float ng = tanhap(hadd2(Ni[rr]) + binn + rg * (hadd2(Nh[rr]) + bhnn));
            float ho = h1s[p][r][j];
            h1s[p ^ 1][r][j] = ng + zg * (ho - ng);
        }
        __syncthreads();   // new h1 visible

        // ========== output head (128 threads) + autoregressive feedback ==========
        if (t >= 0) {
            if (tid < 128) {
                ull acc = 0ull;
                const float* hrow = &h1s[p ^ 1][hr][hl * 16];
                const float* wrow = &was[hs * 128 + hl * 16];
#pragma unroll
                for (int qq = 0; qq < 4; ++qq) {
                    ulonglong2 hv = *reinterpret_cast<const ulonglong2*>(&hrow[qq * 4]);
                    ulonglong2 wv = *reinterpret_cast<const ulonglong2*>(&wrow[qq * 4]);
                    ffma2(acc, wv.x, hv.x);
                    ffma2(acc, wv.y, hv.y);
                }
                float v = hadd2(acc);
                v += __shfl_xor_sync(0xffffffffu, v, 1, 8);
                v += __shfl_xor_sync(0xffffffffu, v, 2, 8);
                v += __shfl_xor_sync(0xffffffffu, v, 4, 8);
                if (hl == 0) {
                    float o = v + bas;
                    decs[hs][hr] = o;
                    out[(size_t)(brow0 + hr) * (TT * 2) + t * 2 + hs] = o;
                }
            }
        } else {
            if (tid < 2 * RPC) {
                int r = tid >> 1, s = tid & 1;
                decs[s][r] = x[(size_t)(brow0 + r) * (TT * 2) + s];
            }
        }
        __syncthreads();   // decs visible for next step's layer-0 epilogue
        p ^= 1;
    }
}

extern "C" void kernel_launch(void* const* d_in, const int* in_sizes, int n_in,
                              void* d_out, int out_size) {
    const float* x       = (const float*)d_in[0];
    const float* noise_z = (const float*)d_in[1];
    const float* context = (const float*)d_in[2];
    const float* Wi0     = (const float*)d_in[3];
    const float* Wh0     = (const float*)d_in[4];
    const float* bi0     = (const float*)d_in[5];
    const float* bh0     = (const float*)d_in[6];
    const float* Wi1     = (const float*)d_in[7];
    const float* Wh1     = (const float*)d_in[8];
    const float* bi1     = (const float*)d_in[9];
    const float* bh1     = (const float*)d_in[10];
    const float* Wa      = (const float*)d_in[11];
    const float* ba      = (const float*)d_in[12];
    float* out = (float*)d_out;

    transpose_k<<<192, 256>>>(Wh0, Wi1, Wh1);
    gru_kernel<<<NCTA, NTHR>>>(x, noise_z, context, Wi0, bi0, bh0,
                               bi1, bh1, Wa, ba, out);
}